// round 5
// baseline (speedup 1.0000x reference)
#include <cuda_runtime.h>
#include <cuda_bf16.h>
#include <cstdint>

// Problem constants: z_e (16,4096,64) f32, embed (1024,64) f32.
#define N_ROWS  65536
#define DIM     64
#define KCODES  1024
#define M_CTA   128
#define NT      64                   // codes per tile
#define NTILES  (KCODES / NT)        // 16
#define THREADS 256
#define NBLOCKS (N_ROWS / M_CTA)     // 512
#define DELTA   0.008f

// smem byte offsets within dynamic smem
#define SM_HNE    0        // 1024 floats  (4096 B)
#define SM_CNT    4096
#define SM_FLAG   4112     // 128 ints
#define SM_ROWIDX 4624     // 128 ints
#define SM_RED    5184     // float[256] + int[256] = 2048 B
#define SM_X      8192     // Xhi 16K + Xlo 16K
#define SM_B      40960    // 2 bufs x (Ehi 8K + Elo 8K) = 32K
#define SMEM_BYTES 73728

__device__ float g_hne[KCODES];          // -0.5 * ||e_k||^2
__device__ float g_partial[NBLOCKS];
__device__ uint4 g_ehi4[KCODES * 8];     // E hi bf16, [code][64] row-major (128B/row)
__device__ uint4 g_elo4[KCODES * 8];     // E lo bf16

// ===================== helpers =====================
__device__ __forceinline__ uint32_t smem_to_u32(const void* p) {
    uint32_t a;
    asm("{ .reg .u64 t; cvta.to.shared.u64 t, %1; cvt.u32.u64 %0, t; }"
        : "=r"(a) : "l"(p));
    return a;
}

__device__ __forceinline__ uint32_t pack_bf2(float a, float b, float& ra, float& rb) {
    __nv_bfloat16 ha = __float2bfloat16_rn(a);
    __nv_bfloat16 hb = __float2bfloat16_rn(b);
    ra = a - __bfloat162float(ha);
    rb = b - __bfloat162float(hb);
    return (uint32_t)__bfloat16_as_ushort(ha) |
           ((uint32_t)__bfloat16_as_ushort(hb) << 16);
}

#define LDSM4(r, addr) \
    asm volatile("ldmatrix.sync.aligned.m8n8.x4.shared.b16 {%0,%1,%2,%3}, [%4];" \
        : "=r"((r)[0]), "=r"((r)[1]), "=r"((r)[2]), "=r"((r)[3]) : "r"(addr))

#define MMA16816(d, a, b0_, b1_) \
    asm volatile("mma.sync.aligned.m16n8k16.row.col.f32.bf16.bf16.f32 " \
        "{%0,%1,%2,%3}, {%4,%5,%6,%7}, {%8,%9}, {%0,%1,%2,%3};" \
        : "+f"((d)[0]), "+f"((d)[1]), "+f"((d)[2]), "+f"((d)[3]) \
        : "r"((a)[0]), "r"((a)[1]), "r"((a)[2]), "r"((a)[3]), "r"(b0_), "r"(b1_))

#define CP_ASYNC16(dst, src) \
    asm volatile("cp.async.cg.shared.global [%0], [%1], 16;" \
        :: "r"(dst), "l"(src) : "memory")
#define CP_COMMIT() asm volatile("cp.async.commit_group;" ::: "memory")
#define CP_WAIT1()  asm volatile("cp.async.wait_group 1;" ::: "memory")
#define CP_WAIT0()  asm volatile("cp.async.wait_group 0;" ::: "memory")

// ===================== kernel 1: prep (norms + bf16 split of E) ============
__global__ void vq_prep_kernel(const float* __restrict__ embed) {
    int k = blockIdx.x * blockDim.x + threadIdx.x;   // 0..1023
    if (k >= KCODES) return;
    const float4* e4 = reinterpret_cast<const float4*>(embed + (size_t)k * DIM);
    float s = 0.f;
#pragma unroll
    for (int j = 0; j < 8; ++j) {
        float4 v0 = e4[2 * j], v1 = e4[2 * j + 1];
        s += v0.x * v0.x + v0.y * v0.y + v0.z * v0.z + v0.w * v0.w +
             v1.x * v1.x + v1.y * v1.y + v1.z * v1.z + v1.w * v1.w;
        float r0, r1, r2, r3, r4, r5, r6, r7;
        uint32_t h0 = pack_bf2(v0.x, v0.y, r0, r1);
        uint32_t h1 = pack_bf2(v0.z, v0.w, r2, r3);
        uint32_t h2 = pack_bf2(v1.x, v1.y, r4, r5);
        uint32_t h3 = pack_bf2(v1.z, v1.w, r6, r7);
        float d0, d1;
        uint32_t l0 = pack_bf2(r0, r1, d0, d1);
        uint32_t l1 = pack_bf2(r2, r3, d0, d1);
        uint32_t l2 = pack_bf2(r4, r5, d0, d1);
        uint32_t l3 = pack_bf2(r6, r7, d0, d1);
        g_ehi4[k * 8 + j] = make_uint4(h0, h1, h2, h3);
        g_elo4[k * 8 + j] = make_uint4(l0, l1, l2, l3);
    }
    g_hne[k] = -0.5f * s;
}

// ===================== kernel 2: main =====================
__device__ __forceinline__ void stage_tile(uint32_t smem_base, int buf, int t, int tid) {
    const char* ghi = reinterpret_cast<const char*>(g_ehi4);
    const char* glo = reinterpret_cast<const char*>(g_elo4);
#pragma unroll
    for (int cc = 0; cc < 2; ++cc) {
        int c = tid + cc * 256;                       // chunk 0..511
        uint32_t rowb = (uint32_t)(c >> 3) * 128u;
        uint32_t col  = ((uint32_t)(c & 7) * 16u) ^ ((((uint32_t)c >> 3) & 7u) << 4);
        uint32_t dst = smem_base + SM_B + (uint32_t)buf * 16384u + rowb + col;
        const char* srch = ghi + ((size_t)t * 512 + c) * 16;
        const char* srcl = glo + ((size_t)t * 512 + c) * 16;
        CP_ASYNC16(dst, srch);
        CP_ASYNC16(dst + 8192, srcl);
    }
}

__global__ __launch_bounds__(THREADS, 2)
void vq_main_kernel(const float* __restrict__ z_e,
                    const float* __restrict__ embed,
                    float* __restrict__ out) {
    extern __shared__ char smem[];
    const uint32_t smem_base = smem_to_u32(smem);

    const int tid  = threadIdx.x;
    const int lane = tid & 31;
    const int wid  = tid >> 5;
    const int row0 = blockIdx.x * M_CTA;

    float* s_hne    = reinterpret_cast<float*>(smem + SM_HNE);
    int*   s_cnt    = reinterpret_cast<int*>(smem + SM_CNT);
    int*   s_flag   = reinterpret_cast<int*>(smem + SM_FLAG);
    int*   s_rowidx = reinterpret_cast<int*>(smem + SM_ROWIDX);
    float* s_rm     = reinterpret_cast<float*>(smem + SM_RED);
    int*   s_ri     = reinterpret_cast<int*>(smem + SM_RED + 1024);

    // Prefetch code tiles 0 and 1 (overlaps with X staging below).
    stage_tile(smem_base, 0, 0, tid); CP_COMMIT();
    stage_tile(smem_base, 1, 1, tid); CP_COMMIT();

    if (tid == 0) *s_cnt = 0;

    // Stage X (128 rows): split fp32 -> bf16 hi/lo, swizzled smem.
    {
        const int xrow = tid >> 1;
        const int hf   = tid & 1;
        const float4* xs = reinterpret_cast<const float4*>(
            z_e + (size_t)(row0 + xrow) * DIM + hf * 32);
        const uint32_t xxor = ((uint32_t)xrow & 7u) << 4;
#pragma unroll
        for (int j = 0; j < 4; ++j) {
            float4 v0 = xs[2 * j], v1 = xs[2 * j + 1];
            float r0, r1, r2, r3, r4, r5, r6, r7;
            uint32_t h0 = pack_bf2(v0.x, v0.y, r0, r1);
            uint32_t h1 = pack_bf2(v0.z, v0.w, r2, r3);
            uint32_t h2 = pack_bf2(v1.x, v1.y, r4, r5);
            uint32_t h3 = pack_bf2(v1.z, v1.w, r6, r7);
            float d0, d1;
            uint32_t l0 = pack_bf2(r0, r1, d0, d1);
            uint32_t l1 = pack_bf2(r2, r3, d0, d1);
            uint32_t l2 = pack_bf2(r4, r5, d0, d1);
            uint32_t l3 = pack_bf2(r6, r7, d0, d1);
            uint32_t col = ((uint32_t)(hf * 64 + j * 16)) ^ xxor;
            *reinterpret_cast<uint4*>(smem + SM_X + xrow * 128 + col) =
                make_uint4(h0, h1, h2, h3);
            *reinterpret_cast<uint4*>(smem + SM_X + 16384 + xrow * 128 + col) =
                make_uint4(l0, l1, l2, l3);
        }
    }
    // Stage hne.
#pragma unroll
    for (int i = 0; i < 4; ++i) s_hne[tid + i * 256] = g_hne[tid + i * 256];
    __syncthreads();

    // A fragments (persist across all tiles): hi + lo, 4 k-chunks.
    uint32_t ah[4][4], al[4][4];
    {
        const uint32_t arow = (uint32_t)(wid * 16 + (lane & 15));
        const uint32_t acs  = (uint32_t)(lane & 16);
        const uint32_t axor = (arow & 7u) << 4;
        const uint32_t abhi = smem_base + SM_X + arow * 128u;
#pragma unroll
        for (int kc = 0; kc < 4; ++kc) {
            uint32_t col = (((uint32_t)(kc * 32)) | acs) ^ axor;
            LDSM4(ah[kc], abhi + col);
            LDSM4(al[kc], abhi + 16384u + col);
        }
    }

    // B address pattern.
    const uint32_t bco  = (uint32_t)((lane & 7) + ((lane & 16) >> 1));
    const uint32_t bcs  = (uint32_t)((lane & 8) << 1);
    const uint32_t bxor = (bco & 7u) << 4;

    float m1l = -3.4e38f, m2l = -3.4e38f, m1h = -3.4e38f, m2h = -3.4e38f;
    int   i1l = 0, i1h = 0;

#pragma unroll 1
    for (int t = 0; t < NTILES; ++t) {
        if (t < NTILES - 1) CP_WAIT1(); else CP_WAIT0();
        __syncthreads();
        const int buf = t & 1;

        float acc[8][4];
#pragma unroll
        for (int nb = 0; nb < 8; ++nb)
#pragma unroll
            for (int q = 0; q < 4; ++q) acc[nb][q] = 0.f;

        const uint32_t bbase = smem_base + SM_B + (uint32_t)buf * 16384u + bco * 128u;
#pragma unroll
        for (int kc = 0; kc < 4; ++kc) {
            const uint32_t col = (((uint32_t)(kc * 32)) | bcs) ^ bxor;
#pragma unroll
            for (int p = 0; p < 4; ++p) {
                uint32_t addr = bbase + (uint32_t)(p * 2048) + col;
                uint32_t bh[4], bl[4];
                LDSM4(bh, addr);
                LDSM4(bl, addr + 8192u);
                MMA16816(acc[2 * p],     ah[kc], bh[0], bh[1]);
                MMA16816(acc[2 * p + 1], ah[kc], bh[2], bh[3]);
                MMA16816(acc[2 * p],     ah[kc], bl[0], bl[1]);
                MMA16816(acc[2 * p + 1], ah[kc], bl[2], bl[3]);
                MMA16816(acc[2 * p],     al[kc], bh[0], bh[1]);
                MMA16816(acc[2 * p + 1], al[kc], bh[2], bh[3]);
            }
        }

        // Score update (top1/top2 per row).
        const int cb0 = t * NT + (lane & 3) * 2;
#pragma unroll
        for (int nb = 0; nb < 8; ++nb) {
            const int cb = cb0 + nb * 8;
            float2 h2 = *reinterpret_cast<const float2*>(&s_hne[cb]);
            float s0 = acc[nb][0] + h2.x;
            float s1 = acc[nb][1] + h2.y;
            float s2 = acc[nb][2] + h2.x;
            float s3 = acc[nb][3] + h2.y;
            if (s0 > m1l) { m2l = m1l; m1l = s0; i1l = cb; }
            else if (s0 > m2l) m2l = s0;
            if (s1 > m1l) { m2l = m1l; m1l = s1; i1l = cb + 1; }
            else if (s1 > m2l) m2l = s1;
            if (s2 > m1h) { m2h = m1h; m1h = s2; i1h = cb; }
            else if (s2 > m2h) m2h = s2;
            if (s3 > m1h) { m2h = m1h; m1h = s3; i1h = cb + 1; }
            else if (s3 > m2h) m2h = s3;
        }
        __syncthreads();
        if (t + 2 < NTILES) { stage_tile(smem_base, buf, t + 2, tid); CP_COMMIT(); }
    }

    // Merge top1/top2 across the 4 lanes sharing each row.
#pragma unroll
    for (int off = 1; off <= 2; off <<= 1) {
        float om1 = __shfl_xor_sync(0xffffffffu, m1l, off);
        float om2 = __shfl_xor_sync(0xffffffffu, m2l, off);
        int   oi  = __shfl_xor_sync(0xffffffffu, i1l, off);
        if (om1 > m1l || (om1 == m1l && oi < i1l)) {
            m2l = fmaxf(m1l, om2); m1l = om1; i1l = oi;
        } else m2l = fmaxf(m2l, om1);
        om1 = __shfl_xor_sync(0xffffffffu, m1h, off);
        om2 = __shfl_xor_sync(0xffffffffu, m2h, off);
        oi  = __shfl_xor_sync(0xffffffffu, i1h, off);
        if (om1 > m1h || (om1 == m1h && oi < i1h)) {
            m2h = fmaxf(m1h, om2); m1h = om1; i1h = oi;
        } else m2h = fmaxf(m2h, om1);
    }
    if ((lane & 3) == 0) {
        const int rlo = wid * 16 + (lane >> 2);
        s_rowidx[rlo] = i1l;
        s_rowidx[rlo + 8] = i1h;
        if (m1l - m2l <= DELTA) { int p = atomicAdd(s_cnt, 1); s_flag[p] = rlo; }
        if (m1h - m2h <= DELTA) { int p = atomicAdd(s_cnt, 1); s_flag[p] = rlo + 8; }
    }
    __syncthreads();

    // Rare exact fp32 rescan for flagged rows (CTA-cooperative).
    const int nf = *s_cnt;
    for (int f = 0; f < nf; ++f) {
        const int r = s_flag[f];
        const float4* x4 = reinterpret_cast<const float4*>(
            z_e + (size_t)(row0 + r) * DIM);
        float xv[DIM];
#pragma unroll
        for (int i = 0; i < DIM / 4; ++i) {
            float4 v = x4[i];
            xv[4 * i] = v.x; xv[4 * i + 1] = v.y;
            xv[4 * i + 2] = v.z; xv[4 * i + 3] = v.w;
        }
        float bm = -3.4e38f; int bidx = 0;
#pragma unroll 1
        for (int c0 = 0; c0 < 4; ++c0) {
            int c = tid * 4 + c0;
            const float4* e4 = reinterpret_cast<const float4*>(
                embed + (size_t)c * DIM);
            float dot = 0.f;
#pragma unroll
            for (int i = 0; i < DIM / 4; ++i) {
                float4 e = e4[i];
                dot += xv[4 * i] * e.x + xv[4 * i + 1] * e.y +
                       xv[4 * i + 2] * e.z + xv[4 * i + 3] * e.w;
            }
            float m = dot + s_hne[c];
            if (m > bm) { bm = m; bidx = c; }
        }
        s_rm[tid] = bm; s_ri[tid] = bidx;
        __syncthreads();
#pragma unroll
        for (int s = 128; s > 0; s >>= 1) {
            if (tid < s) {
                float om = s_rm[tid + s]; int oi = s_ri[tid + s];
                if (om > s_rm[tid] || (om == s_rm[tid] && oi < s_ri[tid])) {
                    s_rm[tid] = om; s_ri[tid] = oi;
                }
            }
            __syncthreads();
        }
        if (tid == 0) s_rowidx[r] = s_ri[0];
        __syncthreads();
    }

    // Epilogue: gather + straight-through + per-row loss.
    float sq = 0.f;
    if (tid < 128) {
        const int grow = row0 + tid;
        const int idx = s_rowidx[tid];
        const float4* q  = reinterpret_cast<const float4*>(embed + (size_t)idx * DIM);
        const float4* x4 = reinterpret_cast<const float4*>(z_e + (size_t)grow * DIM);
        float4* o = reinterpret_cast<float4*>(out + (size_t)grow * DIM);
#pragma unroll
        for (int i = 0; i < DIM / 4; ++i) {
            float4 e = q[i];
            float4 x = x4[i];
            float d0 = e.x - x.x, d1 = e.y - x.y, d2 = e.z - x.z, d3 = e.w - x.w;
            sq += d0 * d0 + d1 * d1 + d2 * d2 + d3 * d3;
            o[i] = make_float4(x.x + d0, x.y + d1, x.z + d2, x.w + d3);
        }
        out[(size_t)N_ROWS * DIM + grow] = (float)idx;
    }

    s_rm[tid] = sq;
    __syncthreads();
#pragma unroll
    for (int s = 128; s > 0; s >>= 1) {
        if (tid < s) s_rm[tid] += s_rm[tid + s];
        __syncthreads();
    }
    if (tid == 0) g_partial[blockIdx.x] = s_rm[0];
}

// ===================== kernel 3: finalize =====================
__global__ void vq_finalize_kernel(float* __restrict__ out) {
    __shared__ float s[NBLOCKS];
    s[threadIdx.x] = g_partial[threadIdx.x];
    __syncthreads();
#pragma unroll
    for (int st = NBLOCKS / 2; st > 0; st >>= 1) {
        if (threadIdx.x < st) s[threadIdx.x] += s[threadIdx.x + st];
        __syncthreads();
    }
    if (threadIdx.x == 0)
        out[(size_t)N_ROWS * DIM + N_ROWS] =
            1.25f * s[0] / (float)((size_t)N_ROWS * DIM);
}

extern "C" void kernel_launch(void* const* d_in, const int* in_sizes, int n_in,
                              void* d_out, int out_size) {
    const float* z_e   = (const float*)d_in[0];
    const float* embed = (const float*)d_in[1];
    float* out = (float*)d_out;
    (void)in_sizes; (void)n_in; (void)out_size;

    cudaFuncSetAttribute(vq_main_kernel,
                         cudaFuncAttributeMaxDynamicSharedMemorySize, SMEM_BYTES);

    vq_prep_kernel<<<KCODES / 256, 256>>>(embed);
    vq_main_kernel<<<NBLOCKS, THREADS, SMEM_BYTES>>>(z_e, embed, out);
    vq_finalize_kernel<<<1, NBLOCKS>>>(out);
}

// round 6
// speedup vs baseline: 1.0994x; 1.0994x over previous
#include <cuda_runtime.h>
#include <cuda_bf16.h>
#include <cstdint>

// Problem constants: z_e (16,4096,64) f32, embed (1024,64) f32.
#define N_ROWS  65536
#define DIM     64
#define KCODES  1024
#define M_CTA   64
#define NT      64
#define NTILES  (KCODES / NT)      // 16
#define THREADS 256
#define NBLOCKS (N_ROWS / M_CTA)   // 1024
#define NCAND   24
#define WCOEF   0.0171875f         // 2 * 1.1 * 2^-7

// smem byte offsets
#define SM_HNE    0        // 1024 f32
#define SM_XF32   4096     // 64x64 f32 = 16384
#define SM_XHI    20480    // 64x128B swizzled bf16
#define SM_B      28672    // 2 x 8192
#define SM_BUF    45056    // 64*24 u32 = 6144
#define SM_CNT    51200    // 64 i32
#define SM_ROWMAX 51456    // 64 u32
#define SM_BEST   51712    // 64 u64 = 512
#define SM_NX     52224    // 64 f32
#define SM_RLIST  52480    // 64 i32
#define SM_NRES   52736    // i32
#define SM_ROWIDX 52752    // 64 i32
#define SM_RED    53024    // 256 f32
#define SM_RI     54048    // 256 i32
#define SMEM_BYTES 55296

__device__ float g_hne[KCODES];        // -0.5 * ||e_k||^2
__device__ float g_partial[NBLOCKS];
__device__ uint4 g_ehi4[KCODES * 8];   // E hi bf16, 8 x uint4 per code (128B/code)
__device__ int   g_emax2i = 0;         // bits of max ||e||^2 (positive floats)

// ===================== helpers =====================
__device__ __forceinline__ uint32_t smem_to_u32(const void* p) {
    uint32_t a;
    asm("{ .reg .u64 t; cvta.to.shared.u64 t, %1; cvt.u32.u64 %0, t; }"
        : "=r"(a) : "l"(p));
    return a;
}
__device__ __forceinline__ uint32_t bf2hi(float a, float b) {
    return (uint32_t)__bfloat16_as_ushort(__float2bfloat16_rn(a)) |
           ((uint32_t)__bfloat16_as_ushort(__float2bfloat16_rn(b)) << 16);
}
__device__ __forceinline__ uint32_t fkey(float f) {
    uint32_t u = __float_as_uint(f);
    return (u & 0x80000000u) ? ~u : (u | 0x80000000u);
}
__device__ __forceinline__ float finv(uint32_t k) {
    uint32_t u = (k & 0x80000000u) ? (k & 0x7fffffffu) : ~k;
    return __uint_as_float(u);
}

#define LDSM4(r, addr) \
    asm volatile("ldmatrix.sync.aligned.m8n8.x4.shared.b16 {%0,%1,%2,%3}, [%4];" \
        : "=r"((r)[0]), "=r"((r)[1]), "=r"((r)[2]), "=r"((r)[3]) : "r"(addr))

#define MMA16816(d, a, b0_, b1_) \
    asm volatile("mma.sync.aligned.m16n8k16.row.col.f32.bf16.bf16.f32 " \
        "{%0,%1,%2,%3}, {%4,%5,%6,%7}, {%8,%9}, {%0,%1,%2,%3};" \
        : "+f"((d)[0]), "+f"((d)[1]), "+f"((d)[2]), "+f"((d)[3]) \
        : "r"((a)[0]), "r"((a)[1]), "r"((a)[2]), "r"((a)[3]), "r"(b0_), "r"(b1_))

#define CP_ASYNC16(dst, src) \
    asm volatile("cp.async.cg.shared.global [%0], [%1], 16;" \
        :: "r"(dst), "l"(src) : "memory")
#define CP_COMMIT() asm volatile("cp.async.commit_group;" ::: "memory")
#define CP_WAIT1()  asm volatile("cp.async.wait_group 1;" ::: "memory")
#define CP_WAIT0()  asm volatile("cp.async.wait_group 0;" ::: "memory")

// ===================== kernel 1: prep =====================
__global__ void vq_prep_kernel(const float* __restrict__ embed) {
    const int g = blockIdx.x * blockDim.x + threadIdx.x;   // 0..4095
    const int code = g >> 2, q = g & 3;
    const float4* e4 = reinterpret_cast<const float4*>(
        embed + (size_t)code * DIM + q * 16);
    float4 v0 = e4[0], v1 = e4[1], v2 = e4[2], v3 = e4[3];
    float s = v0.x*v0.x + v0.y*v0.y + v0.z*v0.z + v0.w*v0.w
            + v1.x*v1.x + v1.y*v1.y + v1.z*v1.z + v1.w*v1.w
            + v2.x*v2.x + v2.y*v2.y + v2.z*v2.z + v2.w*v2.w
            + v3.x*v3.x + v3.y*v3.y + v3.z*v3.z + v3.w*v3.w;
    g_ehi4[code * 8 + q * 2] =
        make_uint4(bf2hi(v0.x, v0.y), bf2hi(v0.z, v0.w),
                   bf2hi(v1.x, v1.y), bf2hi(v1.z, v1.w));
    g_ehi4[code * 8 + q * 2 + 1] =
        make_uint4(bf2hi(v2.x, v2.y), bf2hi(v2.z, v2.w),
                   bf2hi(v3.x, v3.y), bf2hi(v3.z, v3.w));
    s += __shfl_xor_sync(0xffffffffu, s, 1);
    s += __shfl_xor_sync(0xffffffffu, s, 2);
    if (q == 0) {
        g_hne[code] = -0.5f * s;
        atomicMax(&g_emax2i, __float_as_int(s));   // idempotent, deterministic
    }
}

// ===================== kernel 2: main =====================
__device__ __forceinline__ void stage_tile(uint32_t smem_base, int buf, int t, int tid) {
    const char* g = reinterpret_cast<const char*>(g_ehi4);
#pragma unroll
    for (int cc = 0; cc < 2; ++cc) {
        int c = tid * 2 + cc;                              // 0..511
        uint32_t rowb = (uint32_t)(c >> 3) * 128u;
        uint32_t col  = ((uint32_t)(c & 7) * 16u) ^ ((((uint32_t)c >> 3) & 7u) << 4);
        uint32_t dst = smem_base + SM_B + (uint32_t)buf * 8192u + rowb + col;
        CP_ASYNC16(dst, g + ((size_t)t * 512 + c) * 16);
    }
}

__global__ __launch_bounds__(THREADS, 3)
void vq_main_kernel(const float* __restrict__ z_e,
                    const float* __restrict__ embed,
                    float* __restrict__ out) {
    extern __shared__ char smem[];
    const uint32_t smem_base = smem_to_u32(smem);
    const int tid  = threadIdx.x;
    const int lane = tid & 31;
    const int wid  = tid >> 5;
    const int row0 = blockIdx.x * M_CTA;

    float*     s_hne    = reinterpret_cast<float*>(smem + SM_HNE);
    float*     s_xf32   = reinterpret_cast<float*>(smem + SM_XF32);
    uint32_t*  s_buf    = reinterpret_cast<uint32_t*>(smem + SM_BUF);
    int*       s_cnt    = reinterpret_cast<int*>(smem + SM_CNT);
    uint32_t*  s_rowmax = reinterpret_cast<uint32_t*>(smem + SM_ROWMAX);
    unsigned long long* s_best =
        reinterpret_cast<unsigned long long*>(smem + SM_BEST);
    float*     s_nx     = reinterpret_cast<float*>(smem + SM_NX);
    int*       s_rlist  = reinterpret_cast<int*>(smem + SM_RLIST);
    int*       s_nres   = reinterpret_cast<int*>(smem + SM_NRES);
    int*       s_rowidx = reinterpret_cast<int*>(smem + SM_ROWIDX);
    float*     s_rm     = reinterpret_cast<float*>(smem + SM_RED);
    int*       s_ri     = reinterpret_cast<int*>(smem + SM_RI);

    stage_tile(smem_base, 0, 0, tid); CP_COMMIT();
    stage_tile(smem_base, 1, 1, tid); CP_COMMIT();

    if (tid < M_CTA) {
        s_cnt[tid] = 0; s_rowmax[tid] = 0; s_best[tid] = 0ull;
    }
    if (tid == 0) *s_nres = 0;

    // ---- stage X: fp32 copy, row norms, bf16-hi swizzled tile ----
    {
        const int xrow = tid >> 2, q = tid & 3;
        const float4* xs = reinterpret_cast<const float4*>(
            z_e + (size_t)(row0 + xrow) * DIM + q * 16);
        float4 v0 = xs[0], v1 = xs[1], v2 = xs[2], v3 = xs[3];
        float4* xf = reinterpret_cast<float4*>(s_xf32 + xrow * 64 + q * 16);
        xf[0] = v0; xf[1] = v1; xf[2] = v2; xf[3] = v3;
        float nx = v0.x*v0.x + v0.y*v0.y + v0.z*v0.z + v0.w*v0.w
                 + v1.x*v1.x + v1.y*v1.y + v1.z*v1.z + v1.w*v1.w
                 + v2.x*v2.x + v2.y*v2.y + v2.z*v2.z + v2.w*v2.w
                 + v3.x*v3.x + v3.y*v3.y + v3.z*v3.z + v3.w*v3.w;
        nx += __shfl_xor_sync(0xffffffffu, nx, 1);
        nx += __shfl_xor_sync(0xffffffffu, nx, 2);
        if (q == 0) s_nx[xrow] = nx;
        const uint32_t xo = ((uint32_t)(xrow & 7)) << 4;
        *reinterpret_cast<uint4*>(smem + SM_XHI + xrow * 128 +
                                  (((uint32_t)(q * 32)) ^ xo)) =
            make_uint4(bf2hi(v0.x, v0.y), bf2hi(v0.z, v0.w),
                       bf2hi(v1.x, v1.y), bf2hi(v1.z, v1.w));
        *reinterpret_cast<uint4*>(smem + SM_XHI + xrow * 128 +
                                  (((uint32_t)(q * 32 + 16)) ^ xo)) =
            make_uint4(bf2hi(v2.x, v2.y), bf2hi(v2.z, v2.w),
                       bf2hi(v3.x, v3.y), bf2hi(v3.z, v3.w));
    }
#pragma unroll
    for (int i = 0; i < 4; ++i) s_hne[tid + i * 256] = g_hne[tid + i * 256];
    __syncthreads();

    // ---- A fragments ----
    uint32_t ah[4][4];
    {
        const uint32_t arow = (uint32_t)((wid & 3) * 16 + (lane & 15));
        const uint32_t acs  = (uint32_t)(lane & 16);
        const uint32_t axor = (arow & 7u) << 4;
        const uint32_t ab   = smem_base + SM_XHI + arow * 128u;
#pragma unroll
        for (int kc = 0; kc < 4; ++kc)
            LDSM4(ah[kc], ab + (((uint32_t)(kc * 32) | acs) ^ axor));
    }
    const int half = wid >> 2;
    const uint32_t halfoff = (uint32_t)half * 4096u;
    const uint32_t bco  = (uint32_t)((lane & 7) + ((lane & 16) >> 1));
    const uint32_t bcs  = (uint32_t)((lane & 8) << 1);
    const uint32_t bxor = (bco & 7u) << 4;
    const int lq2  = (lane & 3) * 2;
    const int rlo  = (wid & 3) * 16 + (lane >> 2);
    const int rhi  = rlo + 8;

    const float emax = sqrtf(__int_as_float(g_emax2i));
    const float w20 = WCOEF * sqrtf(s_nx[rlo]) * emax;
    const float w21 = WCOEF * sqrtf(s_nx[rhi]) * emax;

    float m0 = -3.4e38f, m1 = -3.4e38f;

    auto mma_tile = [&](int buf, int t, float (&acc)[4][4]) {
        const int cb0 = t * NT + half * 32 + lq2;
#pragma unroll
        for (int nb = 0; nb < 4; ++nb) {
            float2 h = *reinterpret_cast<const float2*>(&s_hne[cb0 + nb * 8]);
            acc[nb][0] = h.x; acc[nb][1] = h.y; acc[nb][2] = h.x; acc[nb][3] = h.y;
        }
        const uint32_t bbase = smem_base + SM_B + (uint32_t)buf * 8192u +
                               halfoff + bco * 128u;
#pragma unroll
        for (int kc = 0; kc < 4; ++kc) {
            const uint32_t col = ((uint32_t)(kc * 32) | bcs) ^ bxor;
#pragma unroll
            for (int p = 0; p < 2; ++p) {
                uint32_t bh[4];
                LDSM4(bh, bbase + (uint32_t)(p * 2048) + col);
                MMA16816(acc[2 * p],     ah[kc], bh[0], bh[1]);
                MMA16816(acc[2 * p + 1], ah[kc], bh[2], bh[3]);
            }
        }
    };

    // ---- warmup: tiles 0,1 raise running max (no inserts) ----
    {
        float acc[4][4];
        CP_WAIT1(); __syncthreads();
        mma_tile(0, 0, acc);
#pragma unroll
        for (int nb = 0; nb < 4; ++nb) {
            m0 = fmaxf(m0, fmaxf(acc[nb][0], acc[nb][1]));
            m1 = fmaxf(m1, fmaxf(acc[nb][2], acc[nb][3]));
        }
        CP_WAIT0(); __syncthreads();
        mma_tile(1, 1, acc);
#pragma unroll
        for (int nb = 0; nb < 4; ++nb) {
            m0 = fmaxf(m0, fmaxf(acc[nb][0], acc[nb][1]));
            m1 = fmaxf(m1, fmaxf(acc[nb][2], acc[nb][3]));
        }
        m0 = fmaxf(m0, __shfl_xor_sync(0xffffffffu, m0, 1));
        m0 = fmaxf(m0, __shfl_xor_sync(0xffffffffu, m0, 2));
        m1 = fmaxf(m1, __shfl_xor_sync(0xffffffffu, m1, 1));
        m1 = fmaxf(m1, __shfl_xor_sync(0xffffffffu, m1, 2));
        atomicMax(&s_rowmax[rlo], fkey(m0));
        atomicMax(&s_rowmax[rhi], fkey(m1));
        __syncthreads();
        m0 = finv(s_rowmax[rlo]);
        m1 = finv(s_rowmax[rhi]);
    }
    float thr0 = m0 - w20, thr1 = m1 - w21;

#define TRY_INS(r_, idx_, s_, m_, thr_, w2_) \
    if ((s_) >= (thr_)) { \
        int pos_ = atomicAdd(&s_cnt[r_], 1); \
        if (pos_ < NCAND) s_buf[(r_) * NCAND + pos_] = (uint32_t)(idx_); \
        if ((s_) > (m_)) { (m_) = (s_); (thr_) = (m_) - (w2_); } \
    }

    // ---- main loop (tiles 0..15, inserts enabled) ----
#pragma unroll 1
    for (int t = 0; t < NTILES; ++t) {
        const int buf = t & 1;
        if (t >= 2) CP_WAIT1();
        __syncthreads();
        float acc[4][4];
        mma_tile(buf, t, acc);

        const int cb0 = t * NT + half * 32 + lq2;
#pragma unroll
        for (int nb = 0; nb < 4; ++nb) {
            const int cb = cb0 + nb * 8;
            TRY_INS(rlo, cb,     acc[nb][0], m0, thr0, w20);
            TRY_INS(rlo, cb + 1, acc[nb][1], m0, thr0, w20);
            TRY_INS(rhi, cb,     acc[nb][2], m1, thr1, w21);
            TRY_INS(rhi, cb + 1, acc[nb][3], m1, thr1, w21);
        }
        // quad-share running max to tighten thresholds
        m0 = fmaxf(m0, __shfl_xor_sync(0xffffffffu, m0, 1));
        m0 = fmaxf(m0, __shfl_xor_sync(0xffffffffu, m0, 2));
        m1 = fmaxf(m1, __shfl_xor_sync(0xffffffffu, m1, 1));
        m1 = fmaxf(m1, __shfl_xor_sync(0xffffffffu, m1, 2));
        thr0 = m0 - w20; thr1 = m1 - w21;

        __syncthreads();
        if (t + 2 < NTILES) { stage_tile(smem_base, buf, t + 2, tid); CP_COMMIT(); }
    }
    __syncthreads();

    // ---- collect overflow rows ----
    if (tid < M_CTA && s_cnt[tid] > NCAND) {
        int p = atomicAdd(s_nres, 1);
        s_rlist[p] = tid;
    }
    __syncthreads();

    // ---- exact fp32 rescore of buffered candidates ----
    const float4* xf4 = reinterpret_cast<const float4*>(s_xf32);
#pragma unroll 1
    for (int j = tid; j < M_CTA * NCAND; j += THREADS) {
        const int r = j / NCAND, c = j % NCAND;
        const int cr = s_cnt[r];
        if (cr > NCAND || c >= cr) continue;
        const int idx = (int)s_buf[r * NCAND + c];
        const float4* e4 = reinterpret_cast<const float4*>(
            embed + (size_t)idx * DIM);
        float dot = 0.f;
#pragma unroll
        for (int i = 0; i < 16; ++i) {
            float4 e = e4[i];
            float4 x = xf4[r * 16 + i];
            dot += x.x * e.x + x.y * e.y + x.z * e.z + x.w * e.w;
        }
        unsigned long long pk =
            ((unsigned long long)fkey(dot + s_hne[idx]) << 32) |
            (unsigned long long)(uint32_t)(1023 - idx);
        atomicMax(&s_best[r], pk);
    }
    __syncthreads();
    if (tid < M_CTA)
        s_rowidx[tid] = 1023 - (int)(uint32_t)(s_best[tid] & 0xffffffffull);
    __syncthreads();

    // ---- full exact rescan for overflow rows (rare) ----
    const int nres = *s_nres;
#pragma unroll 1
    for (int f = 0; f < nres; ++f) {
        const int r = s_rlist[f];
        float bm = -3.4e38f; int bidx = 0;
#pragma unroll 1
        for (int c0 = 0; c0 < 4; ++c0) {
            const int c = tid * 4 + c0;
            const float4* e4 = reinterpret_cast<const float4*>(
                embed + (size_t)c * DIM);
            float dot = 0.f;
#pragma unroll
            for (int i = 0; i < 16; ++i) {
                float4 e = e4[i];
                float4 x = xf4[r * 16 + i];
                dot += x.x * e.x + x.y * e.y + x.z * e.z + x.w * e.w;
            }
            float m = dot + s_hne[c];
            if (m > bm) { bm = m; bidx = c; }
        }
        s_rm[tid] = bm; s_ri[tid] = bidx;
        __syncthreads();
#pragma unroll
        for (int s = 128; s > 0; s >>= 1) {
            if (tid < s) {
                float om = s_rm[tid + s]; int oi = s_ri[tid + s];
                if (om > s_rm[tid] || (om == s_rm[tid] && oi < s_ri[tid])) {
                    s_rm[tid] = om; s_ri[tid] = oi;
                }
            }
            __syncthreads();
        }
        if (tid == 0) s_rowidx[r] = s_ri[0];
        __syncthreads();
    }

    // ---- epilogue: gather + straight-through + loss (4 threads/row) ----
    float sq = 0.f;
    {
        const int r = tid >> 2, q = tid & 3;
        const int grow = row0 + r;
        const int idx = s_rowidx[r];
        const float4* e4 = reinterpret_cast<const float4*>(
            embed + (size_t)idx * DIM + q * 16);
        float4* o = reinterpret_cast<float4*>(out + (size_t)grow * DIM + q * 16);
#pragma unroll
        for (int i = 0; i < 4; ++i) {
            float4 e = e4[i];
            float4 x = xf4[r * 16 + q * 4 + i];
            float d0 = e.x - x.x, d1 = e.y - x.y, d2 = e.z - x.z, d3 = e.w - x.w;
            sq += d0 * d0 + d1 * d1 + d2 * d2 + d3 * d3;
            o[i] = make_float4(x.x + d0, x.y + d1, x.z + d2, x.w + d3);
        }
        if (q == 0) out[(size_t)N_ROWS * DIM + grow] = (float)idx;
    }

    s_rm[tid] = sq;
    __syncthreads();
#pragma unroll
    for (int s = 128; s > 0; s >>= 1) {
        if (tid < s) s_rm[tid] += s_rm[tid + s];
        __syncthreads();
    }
    if (tid == 0) g_partial[blockIdx.x] = s_rm[0];
}

// ===================== kernel 3: finalize =====================
__global__ void vq_finalize_kernel(float* __restrict__ out) {
    __shared__ float s[NBLOCKS];
    s[threadIdx.x] = g_partial[threadIdx.x];
    __syncthreads();
#pragma unroll
    for (int st = NBLOCKS / 2; st > 0; st >>= 1) {
        if (threadIdx.x < st) s[threadIdx.x] += s[threadIdx.x + st];
        __syncthreads();
    }
    if (threadIdx.x == 0)
        out[(size_t)N_ROWS * DIM + N_ROWS] =
            1.25f * s[0] / (float)((size_t)N_ROWS * DIM);
}

extern "C" void kernel_launch(void* const* d_in, const int* in_sizes, int n_in,
                              void* d_out, int out_size) {
    const float* z_e   = (const float*)d_in[0];
    const float* embed = (const float*)d_in[1];
    float* out = (float*)d_out;
    (void)in_sizes; (void)n_in; (void)out_size;

    cudaFuncSetAttribute(vq_main_kernel,
                         cudaFuncAttributeMaxDynamicSharedMemorySize, SMEM_BYTES);

    vq_prep_kernel<<<16, 256>>>(embed);
    vq_main_kernel<<<NBLOCKS, THREADS, SMEM_BYTES>>>(z_e, embed, out);
    vq_finalize_kernel<<<1, NBLOCKS>>>(out);
}